// round 1
// baseline (speedup 1.0000x reference)
#include <cuda_runtime.h>
#include <cstdint>
#include <cstddef>

#define NPTS 80000
#define H    32
#define KPTS 15
#define CIN  128
#define COUT 256
#define D2   64
#define INFL 0.4f
#define EPS  1e-5f
#define SLOPE 0.2f

// ---------------- device scratch (no allocs allowed) ----------------
__device__ __align__(128) float g_x1 [(size_t)NPTS * D2];          // y1 raw, then BN+act in place
__device__ __align__(128) float g_fk [(size_t)NPTS * KPTS * D2];   // [n][k*64+d]  (307 MB)
__device__ __align__(128) float g_xkp[(size_t)NPTS * D2];          // KPConv output
__device__ __align__(128) float g_y2 [(size_t)NPTS * COUT];        // pre-BN unary_2
__device__ __align__(128) float g_part[256 * 2 * COUT];            // per-block column partials
__device__ __align__(128) float g_bn1 [2 * D2];                    // scale, shift
__device__ __align__(128) float g_bn2 [2 * COUT];
__device__ __align__(128) float g_bnsc[2 * COUT];

__device__ __forceinline__ float leaky(float v) {
    return v > 0.f ? v : v * SLOPE;
}

// ---------------- generic register-tiled fp32 GEMM ----------------
// C[M x ND] = A[M x KD] @ B[KD x ND], row-major. Block tile 64x64, thread 4x4.
template<int KD, int ND>
__global__ __launch_bounds__(256)
void gemm_k(const float* __restrict__ A, const float* __restrict__ B,
            float* __restrict__ C) {
    __shared__ float sA[32][65];   // [k][r], padded
    __shared__ float sB[32][64];   // [k][c]
    const int row0 = blockIdx.x * 64;
    const int col0 = blockIdx.y * 64;
    const int tid  = threadIdx.x;
    const int tx   = tid & 15;     // -> col group
    const int ty   = tid >> 4;     // -> row group
    const int rr   = ty * 4;
    const int cc   = tx * 4;

    float acc[4][4];
#pragma unroll
    for (int i = 0; i < 4; i++)
#pragma unroll
        for (int j = 0; j < 4; j++) acc[i][j] = 0.f;

    for (int k0 = 0; k0 < KD; k0 += 32) {
        // A tile: 64 rows x 32 k, stored transposed sA[k][r]
        {
            const int r  = tid >> 3;          // 0..31
            const int k4 = (tid & 7) * 4;     // 0..28
#pragma unroll
            for (int pass = 0; pass < 2; pass++) {
                const int rg = r + pass * 32;
                float4 v = *(const float4*)&A[(size_t)(row0 + rg) * KD + k0 + k4];
                sA[k4 + 0][rg] = v.x;
                sA[k4 + 1][rg] = v.y;
                sA[k4 + 2][rg] = v.z;
                sA[k4 + 3][rg] = v.w;
            }
        }
        // B tile: 32 k x 64 c
        {
            const int kB = tid >> 4;          // 0..15
            const int c4 = (tid & 15) * 4;    // 0..60
#pragma unroll
            for (int pass = 0; pass < 2; pass++) {
                const int kk = kB + pass * 16;
                float4 v = *(const float4*)&B[(size_t)(k0 + kk) * ND + col0 + c4];
                *(float4*)&sB[kk][c4] = v;
            }
        }
        __syncthreads();
#pragma unroll
        for (int kk = 0; kk < 32; kk++) {
            const float a0 = sA[kk][rr + 0];
            const float a1 = sA[kk][rr + 1];
            const float a2 = sA[kk][rr + 2];
            const float a3 = sA[kk][rr + 3];
            const float4 b = *(const float4*)&sB[kk][cc];
            acc[0][0] += a0 * b.x; acc[0][1] += a0 * b.y; acc[0][2] += a0 * b.z; acc[0][3] += a0 * b.w;
            acc[1][0] += a1 * b.x; acc[1][1] += a1 * b.y; acc[1][2] += a1 * b.z; acc[1][3] += a1 * b.w;
            acc[2][0] += a2 * b.x; acc[2][1] += a2 * b.y; acc[2][2] += a2 * b.z; acc[2][3] += a2 * b.w;
            acc[3][0] += a3 * b.x; acc[3][1] += a3 * b.y; acc[3][2] += a3 * b.z; acc[3][3] += a3 * b.w;
        }
        __syncthreads();
    }
#pragma unroll
    for (int i = 0; i < 4; i++) {
        float4 v = make_float4(acc[i][0], acc[i][1], acc[i][2], acc[i][3]);
        *(float4*)&C[(size_t)(row0 + rr + i) * ND + col0 + cc] = v;
    }
}

// ---------------- column stats (deterministic 2-stage) ----------------
template<int C>
__global__ __launch_bounds__(256)
void colstats(const float* __restrict__ y, float* __restrict__ part) {
    const int tid = threadIdx.x, bid = blockIdx.x;
    if (C == 256) {
        float s = 0.f, q = 0.f;
        for (int r = bid; r < NPTS; r += 256) {
            float v = y[(size_t)r * 256 + tid];
            s += v; q += v * v;
        }
        part[bid * 512 + tid]       = s;
        part[bid * 512 + 256 + tid] = q;
    } else {
        const int c = tid & 63, rg = tid >> 6;
        float s = 0.f, q = 0.f;
        for (int r = bid * 4 + rg; r < NPTS; r += 1024) {
            float v = y[(size_t)r * 64 + c];
            s += v; q += v * v;
        }
        __shared__ float sh[2][256];
        sh[0][tid] = s; sh[1][tid] = q;
        __syncthreads();
        if (tid < 64) {
            s = sh[0][tid] + sh[0][tid + 64] + sh[0][tid + 128] + sh[0][tid + 192];
            q = sh[1][tid] + sh[1][tid + 64] + sh[1][tid + 128] + sh[1][tid + 192];
            part[bid * 128 + tid]      = s;
            part[bid * 128 + 64 + tid] = q;
        }
    }
}

template<int C>
__global__ void finalize_bn(const float* __restrict__ part,
                            const float* __restrict__ g, const float* __restrict__ b,
                            float* __restrict__ bnout) {
    const int c = threadIdx.x;
    float s = 0.f, q = 0.f;
    for (int i = 0; i < 256; i++) {
        s += part[i * 2 * C + c];
        q += part[i * 2 * C + C + c];
    }
    const float mean = s / (float)NPTS;
    const float var  = q / (float)NPTS - mean * mean;
    const float sc   = g[c] * rsqrtf(var + EPS);
    bnout[c]     = sc;
    bnout[C + c] = b[c] - mean * sc;
}

// ---------------- BN1 apply + leaky relu (in place on g_x1) ----------------
__global__ __launch_bounds__(256)
void bn_act_64(float* __restrict__ x, const float* __restrict__ bn) {
    const size_t i = (size_t)blockIdx.x * 256 + threadIdx.x;   // float4 index
    float4 v = ((float4*)x)[i];
    const int c = (int)((i * 4) & 63);
    v.x = leaky(v.x * bn[c + 0] + bn[64 + c + 0]);
    v.y = leaky(v.y * bn[c + 1] + bn[64 + c + 1]);
    v.z = leaky(v.z * bn[c + 2] + bn[64 + c + 2]);
    v.w = leaky(v.w * bn[c + 3] + bn[64 + c + 3]);
    ((float4*)x)[i] = v;
}

// ---------------- KPConv: influence weights + fk accumulation ----------------
// 16 points/block, 256 threads. Phase 1: w[p][h][k] in smem. Phase 2: 16 threads
// per point, each owns a float4 d-slice and all 15 k accumulators in registers.
__global__ __launch_bounds__(256)
void kpconv_kernel(const float* __restrict__ xyz, const int* __restrict__ nbr,
                   const float* __restrict__ kp) {
    __shared__ float s_kp[KPTS * 3];
    __shared__ int   s_nbr[16][H];
    __shared__ float s_w[16 * 481];   // p*481 + h*15 + k  (481 kills bank conflicts)

    const int tid = threadIdx.x;
    const int n0  = blockIdx.x * 16;

    if (tid < KPTS * 3) s_kp[tid] = kp[tid];
    __syncthreads();

    // phase 1: 512 (p,h) tasks
    for (int t = tid; t < 512; t += 256) {
        const int p = t >> 5, h = t & 31;
        const int n = n0 + p;
        const int j = nbr[n * H + h];
        s_nbr[p][h] = j;
        const float dx = xyz[j * 3 + 0] - xyz[n * 3 + 0];
        const float dy = xyz[j * 3 + 1] - xyz[n * 3 + 1];
        const float dz = xyz[j * 3 + 2] - xyz[n * 3 + 2];
        float* wp = &s_w[p * 481 + h * 15];
#pragma unroll
        for (int k = 0; k < KPTS; k++) {
            const float ex = dx - s_kp[k * 3 + 0];
            const float ey = dy - s_kp[k * 3 + 1];
            const float ez = dz - s_kp[k * 3 + 2];
            const float sq = ex * ex + ey * ey + ez * ez;
            wp[k] = fmaxf(1.f - sqrtf(sq) * (1.f / INFL), 0.f);
        }
    }
    __syncthreads();

    // phase 2
    const int p   = tid >> 4;
    const int d0  = (tid & 15) * 4;
    const int n   = n0 + p;
    float acc[KPTS][4];
#pragma unroll
    for (int k = 0; k < KPTS; k++) {
        acc[k][0] = 0.f; acc[k][1] = 0.f; acc[k][2] = 0.f; acc[k][3] = 0.f;
    }
    const float* wrow = &s_w[p * 481];
    for (int h = 0; h < H; h++) {
        const int j = s_nbr[p][h];
        const float4 v = *(const float4*)&g_x1[(size_t)j * 64 + d0];
        const float* wp = wrow + h * 15;
#pragma unroll
        for (int k = 0; k < KPTS; k++) {
            const float w = wp[k];
            acc[k][0] += w * v.x;
            acc[k][1] += w * v.y;
            acc[k][2] += w * v.z;
            acc[k][3] += w * v.w;
        }
    }
    float* dst = &g_fk[(size_t)n * (KPTS * 64) + d0];
#pragma unroll
    for (int k = 0; k < KPTS; k++) {
        *(float4*)&dst[k * 64] = make_float4(acc[k][0], acc[k][1], acc[k][2], acc[k][3]);
    }
}

// ---------------- final combine: leaky(BN2(y2)) + BNsc(sc) ----------------
__global__ __launch_bounds__(256)
void combine_kernel(const float* __restrict__ y2, float* __restrict__ out,
                    const float* __restrict__ bn2, const float* __restrict__ bnsc) {
    const size_t i = (size_t)blockIdx.x * 256 + threadIdx.x;   // float4 index
    const int c = (int)((i * 4) & 255);
    float4 a = ((const float4*)y2)[i];
    float4 s = ((float4*)out)[i];
    float4 r;
    r.x = leaky(a.x * bn2[c + 0] + bn2[256 + c + 0]) + (s.x * bnsc[c + 0] + bnsc[256 + c + 0]);
    r.y = leaky(a.y * bn2[c + 1] + bn2[256 + c + 1]) + (s.y * bnsc[c + 1] + bnsc[256 + c + 1]);
    r.z = leaky(a.z * bn2[c + 2] + bn2[256 + c + 2]) + (s.z * bnsc[c + 2] + bnsc[256 + c + 2]);
    r.w = leaky(a.w * bn2[c + 3] + bn2[256 + c + 3]) + (s.w * bnsc[c + 3] + bnsc[256 + c + 3]);
    ((float4*)out)[i] = r;
}

// ---------------- launcher ----------------
extern "C" void kernel_launch(void* const* d_in, const int* in_sizes, int n_in,
                              void* d_out, int out_size) {
    const float* feats = (const float*)d_in[0];
    const float* xyz   = (const float*)d_in[1];
    // d_in[2] = batch (unused, single batch)
    const int*   nbr   = (const int*)d_in[3];
    const float* W1    = (const float*)d_in[4];
    const float* g1    = (const float*)d_in[5];
    const float* b1    = (const float*)d_in[6];
    const float* kpp   = (const float*)d_in[7];
    const float* kpw   = (const float*)d_in[8];   // [15,64,64] -> [960][64]
    const float* W2    = (const float*)d_in[9];
    const float* g2    = (const float*)d_in[10];
    const float* b2    = (const float*)d_in[11];
    const float* Wsc   = (const float*)d_in[12];
    const float* gsc   = (const float*)d_in[13];
    const float* bsc   = (const float*)d_in[14];
    float* out = (float*)d_out;

    void *p_x1, *p_fk, *p_xkp, *p_y2, *p_part, *p_bn1, *p_bn2, *p_bnsc;
    cudaGetSymbolAddress(&p_x1,  g_x1);
    cudaGetSymbolAddress(&p_fk,  g_fk);
    cudaGetSymbolAddress(&p_xkp, g_xkp);
    cudaGetSymbolAddress(&p_y2,  g_y2);
    cudaGetSymbolAddress(&p_part, g_part);
    cudaGetSymbolAddress(&p_bn1, g_bn1);
    cudaGetSymbolAddress(&p_bn2, g_bn2);
    cudaGetSymbolAddress(&p_bnsc, g_bnsc);
    float* x1p  = (float*)p_x1;
    float* fkp  = (float*)p_fk;
    float* xkpp = (float*)p_xkp;
    float* y2p  = (float*)p_y2;
    float* part = (float*)p_part;
    float* bn1  = (float*)p_bn1;
    float* bn2  = (float*)p_bn2;
    float* bnsc = (float*)p_bnsc;

    // 1) unary_1 GEMM: y1 = feats @ W1  [N,64]
    gemm_k<128, 64><<<dim3(1250, 1), 256>>>(feats, W1, x1p);
    // 2) BN1 stats + apply + act (in place)
    colstats<64><<<256, 256>>>(x1p, part);
    finalize_bn<64><<<1, 64>>>(part, g1, b1, bn1);
    bn_act_64<<<NPTS * 64 / 4 / 256, 256>>>(x1p, bn1);
    // 3) KPConv accumulate -> fk [N, 960]
    kpconv_kernel<<<NPTS / 16, 256>>>(xyz, nbr, kpp);
    // 4) fk @ kp_weights  [N,960]@[960,64]
    gemm_k<960, 64><<<dim3(1250, 1), 256>>>(fkp, kpw, xkpp);
    // 5) unary_2 GEMM: y2 = xkp @ W2  [N,256]
    gemm_k<64, 256><<<dim3(1250, 4), 256>>>(xkpp, W2, y2p);
    colstats<256><<<256, 256>>>(y2p, part);
    finalize_bn<256><<<1, 256>>>(part, g2, b2, bn2);
    // 6) shortcut GEMM raw -> out
    gemm_k<128, 256><<<dim3(1250, 4), 256>>>(feats, Wsc, out);
    colstats<256><<<256, 256>>>(out, part);
    finalize_bn<256><<<1, 256>>>(part, gsc, bsc, bnsc);
    // 7) out = leaky(BN2(y2)) + BNsc(shortcut)
    combine_kernel<<<NPTS * 256 / 4 / 256, 256>>>(y2p, out, bn2, bnsc);
}